// round 9
// baseline (speedup 1.0000x reference)
#include <cuda_runtime.h>
#include <cstdint>

// ---------------------------------------------------------------------------
// Problem constants
// ---------------------------------------------------------------------------
#define N_R       2000
#define N_P       1512
#define M_TOT     3512
#define SIZE_R    3000
#define FUN_IN    5603
#define ATT_H     2048
#define FUN_H     4096
#define DFEAT     512
#define BATCH     8192
#define KP_ATT    3008          // SIZE_R padded to 16
#define KP_FUN    5616          // FUN_IN padded to 16 (5603 -> 5616)

#define EP_OFF    (N_R * DFEAT)
#define OUT2_OFF  (EP_OFF + N_P * DFEAT)
#define FLAT_OFF  (OUT2_OFF + BATCH * 2)

// ---------------------------------------------------------------------------
// fp32 scratch
// ---------------------------------------------------------------------------
__device__ __align__(256) float gAatt[(size_t)M_TOT * KP_ATT];   // 42 MB
__device__ __align__(256) float gAfun[(size_t)M_TOT * KP_FUN];   // 79 MB
__device__ __align__(256) float gHa[(size_t)M_TOT * ATT_H];      // 29 MB
__device__ __align__(256) float gHf[(size_t)M_TOT * FUN_H];      // 58 MB

// ---------------------------------------------------------------------------
// concat + pad copy:  dst(M, Kpad) = [A0; A1] with zero pad
// ---------------------------------------------------------------------------
__global__ void convA_f32(const float* __restrict__ A0, const float* __restrict__ A1,
                          int split, int K, int Kpad, float* __restrict__ dst)
{
    const int k = blockIdx.x * 256 + threadIdx.x;
    const int m = blockIdx.y;
    if (k >= Kpad) return;
    float x = 0.0f;
    if (k < K)
        x = (m < split) ? A0[(size_t)m * K + k] : A1[(size_t)(m - split) * K + k];
    dst[(size_t)m * Kpad + k] = x;
}

// ---------------------------------------------------------------------------
// SIMT fp32 SGEMM: C(M,N) = act( A(M,lda) @ W(K,N) + bias )
//   A padded (reads always in-bounds, pad contributes 0); W rows >= Kreal zero.
//   BM=128, BK=16, 256 threads, per-thread TM=8 x TN (8 or 4).
// EPI 0: gelu  -> H[gm*ldh + gn]
// EPI 1: sigmoid -> scatter to d_out e_r/e_p at column colOff+gn
// ---------------------------------------------------------------------------
template <int BN, int TN, int EPI>
__global__ __launch_bounds__(256, 2)
void sgemm_k(const float* __restrict__ A, int lda, int M, int Kpad, int Kreal,
             const float* __restrict__ W, int N,
             const float* __restrict__ bias,
             float* __restrict__ outp, float* __restrict__ H, int ldh, int colOff)
{
    constexpr int BM = 128, BK = 16, TM = 8;
    constexpr int ASTR = BM + 4;            // 132 (pad: STS conflicts <= 2-way)
    constexpr int NF = BN / 64;             // B float4s per thread (2 or 1)
    static_assert((BM / TM) * (BN / TN) == 256, "256 threads");

    __shared__ float As[2][BK * ASTR];
    __shared__ float Bs[2][BK * BN];

    const int tid = threadIdx.x;
    const int tx  = tid & 15;               // BN/TN == 16 for both configs
    const int ty  = tid >> 4;
    const int bm0 = blockIdx.y * BM;
    const int bn0 = blockIdx.x * BN;

    // A load mapping: thread covers row arow, k in [ak, ak+8)
    const int arow = tid >> 1;
    const int ak   = (tid & 1) * 8;
    int gmA = bm0 + arow; if (gmA >= M) gmA = M - 1;   // clamp; results discarded
    const float* Aptr = A + (size_t)gmA * lda + ak;

    // B load mapping: thread covers row bkr, NF float4s along n
    const int bkr = tid >> 4;
    const int bnf = tid & 15;

    float4 ra0, ra1, rb[NF];

    float acc[TM][TN];
#pragma unroll
    for (int i = 0; i < TM; ++i)
#pragma unroll
        for (int j = 0; j < TN; ++j) acc[i][j] = 0.0f;

    auto ldg = [&](int kt) {
        ra0 = *reinterpret_cast<const float4*>(Aptr + kt);
        ra1 = *reinterpret_cast<const float4*>(Aptr + kt + 4);
        const int gk = kt + bkr;
        if (gk < Kreal) {
            const float* Wr = W + (size_t)gk * N + bn0;
#pragma unroll
            for (int f = 0; f < NF; ++f)
                rb[f] = *reinterpret_cast<const float4*>(Wr + (bnf + f * 16) * 4);
        } else {
#pragma unroll
            for (int f = 0; f < NF; ++f) rb[f] = make_float4(0.f, 0.f, 0.f, 0.f);
        }
    };
    auto sts = [&](int b) {
        float av[8] = {ra0.x, ra0.y, ra0.z, ra0.w, ra1.x, ra1.y, ra1.z, ra1.w};
#pragma unroll
        for (int i = 0; i < 8; ++i)
            As[b][(ak + i) * ASTR + arow] = av[i];
#pragma unroll
        for (int f = 0; f < NF; ++f)
            *reinterpret_cast<float4*>(&Bs[b][bkr * BN + (bnf + f * 16) * 4]) = rb[f];
    };

    const int nc = Kpad / BK;
    ldg(0);
    sts(0);
    __syncthreads();

    for (int c = 0; c < nc; ++c) {
        if (c + 1 < nc) ldg((c + 1) * BK);     // overlap gmem with compute
        const int cur = c & 1;
#pragma unroll
        for (int k = 0; k < BK; ++k) {
            float a[TM], b[TN];
            *reinterpret_cast<float4*>(&a[0]) =
                *reinterpret_cast<const float4*>(&As[cur][k * ASTR + ty * 4]);
            *reinterpret_cast<float4*>(&a[4]) =
                *reinterpret_cast<const float4*>(&As[cur][k * ASTR + ty * 4 + 64]);
            *reinterpret_cast<float4*>(&b[0]) =
                *reinterpret_cast<const float4*>(&Bs[cur][k * BN + tx * 4]);
            if constexpr (TN == 8)
                *reinterpret_cast<float4*>(&b[4]) =
                    *reinterpret_cast<const float4*>(&Bs[cur][k * BN + tx * 4 + 64]);
#pragma unroll
            for (int i = 0; i < TM; ++i)
#pragma unroll
                for (int j = 0; j < TN; ++j)
                    acc[i][j] = fmaf(a[i], b[j], acc[i][j]);
        }
        if (c + 1 < nc) sts((c + 1) & 1);      // writes the OTHER buffer: safe pre-sync
        __syncthreads();
    }

    // ---- epilogue ----
#pragma unroll
    for (int i = 0; i < TM; ++i) {
        const int gm = bm0 + ty * 4 + (i & 3) + (i >> 2) * 64;
        if (gm >= M) continue;
#pragma unroll
        for (int j = 0; j < TN; ++j) {
            const int gn = bn0 + tx * 4 + (j & 3) + (j >> 2) * 64;
            const float v = acc[i][j] + __ldg(bias + gn);
            if constexpr (EPI == 0) {
                H[(size_t)gm * ldh + gn] =
                    0.5f * v * (1.0f + erff(v * 0.70710678118654752f));
            } else {
                float* dst = (gm < N_R)
                                 ? (outp + (size_t)gm * DFEAT + colOff + gn)
                                 : (outp + EP_OFF + (size_t)(gm - N_R) * DFEAT + colOff + gn);
                *dst = 1.0f / (1.0f + expf(-v));
            }
        }
    }
}

// ---------------------------------------------------------------------------
// CNN head (unchanged from round 1)
// ---------------------------------------------------------------------------
#define SMX    0
#define SMW1   (SMX  + 2 * 516)
#define SMB1   (SMW1 + 240)
#define SMB2   (SMB1 + 16)
#define SMW2   (SMB2 + 32)
#define SMP1   (SMW2 + 7680)
#define SMRED  (SMP1 + 16 * 2 * 260)
#define SMTOT  (SMRED + 16)

__global__ __launch_bounds__(256)
void conv_head_k(const float* __restrict__ w1, const float* __restrict__ b1,
                 const float* __restrict__ w2, const float* __restrict__ b2,
                 const int* __restrict__ idx,
                 const float* __restrict__ Wout, const float* __restrict__ bout,
                 float* __restrict__ out)
{
    extern __shared__ float smf[];
    float* s_x  = smf + SMX;
    float* s_w1 = smf + SMW1;
    float* s_b1 = smf + SMB1;
    float* s_b2 = smf + SMB2;
    float* s_w2 = smf + SMW2;
    float* s_p1 = smf + SMP1;
    float* s_red = smf + SMRED;

    const int tid = threadIdx.x;
    const int b   = blockIdx.x;

    for (int i = tid; i < 2 * 516; i += 256) s_x[i] = 0.0f;
    for (int i = tid; i < 16 * 2 * 260; i += 256) s_p1[i] = 0.0f;
    for (int i = tid; i < 240; i += 256) s_w1[i] = w1[i];
    for (int i = tid; i < 7680; i += 256) s_w2[i] = w2[i];
    if (tid < 16) s_b1[tid] = b1[tid];
    if (tid >= 32 && tid < 64) s_b2[tid - 32] = b2[tid - 32];

    const int id   = idx[b];
    const int r_no = id / 1512;
    const int p_no = id - r_no * 1512;
    __syncthreads();

    for (int c = tid; c < DFEAT; c += 256) {
        s_x[2 + c]        = out[(size_t)r_no * DFEAT + c];
        s_x[516 + 2 + c]  = out[EP_OFF + (size_t)p_no * DFEAT + c];
    }
    __syncthreads();

    for (int j = tid; j < 16 * 2 * 256; j += 256) {
        const int oc = j >> 9;
        const int ph = (j >> 8) & 1;
        const int pw = j & 255;
        const float* w = s_w1 + oc * 15;
        const float bv = s_b1[oc];
        float sum = 0.0f;
#pragma unroll
        for (int dh = 0; dh < 2; ++dh) {
            const int oh = 2 * ph + dh;
#pragma unroll
            for (int dw = 0; dw < 2; ++dw) {
                const int ow = 2 * pw + dw;
                float c = 0.0f;
#pragma unroll
                for (int kh = 0; kh < 3; ++kh) {
                    const int ih = oh + kh - 2;
                    if (ih >= 0 && ih < 2) {
#pragma unroll
                        for (int kw = 0; kw < 5; ++kw)
                            c = fmaf(w[kh * 5 + kw], s_x[ih * 516 + ow + kw], c);
                    }
                }
                c += bv;
                sum += (c >= 0.0f) ? c : 0.01f * c;
            }
        }
        s_p1[(oc * 2 + ph) * 260 + 2 + pw] = 0.25f * sum;
    }
    __syncthreads();

    float ro0 = 0.0f, ro1 = 0.0f;
#pragma unroll
    for (int pass = 0; pass < 4; ++pass) {
        const int t   = tid + pass * 256;
        const int ocg = t >> 7;
        const int ph  = (t >> 6) & 1;
        const int pwg = t & 63;
        const int ow0 = pwg * 4;

        float accA[4][4], accB[4][4];
#pragma unroll
        for (int o = 0; o < 4; ++o)
#pragma unroll
            for (int j = 0; j < 4; ++j) { accA[o][j] = 0.0f; accB[o][j] = 0.0f; }

        const int khA0 = 2 - 2 * ph;
#pragma unroll
        for (int ic = 0; ic < 16; ++ic) {
#pragma unroll
            for (int ih = 0; ih < 2; ++ih) {
                const float* rowp = s_p1 + (ic * 2 + ih) * 260;
                float4 u0 = *reinterpret_cast<const float4*>(rowp + ow0);
                float4 u1 = *reinterpret_cast<const float4*>(rowp + ow0 + 4);
                float in[8] = {u0.x, u0.y, u0.z, u0.w, u1.x, u1.y, u1.z, u1.w};

                const int khA = ih + khA0;
                if (khA >= 0 && khA < 3) {
#pragma unroll
                    for (int o = 0; o < 4; ++o) {
                        const float* w = s_w2 + ((((ocg * 4 + o) * 16 + ic) * 3 + khA) * 5);
#pragma unroll
                        for (int kw = 0; kw < 5; ++kw) {
                            const float wv = w[kw];
#pragma unroll
                            for (int j = 0; j < 4; ++j)
                                accA[o][j] = fmaf(wv, in[j + kw], accA[o][j]);
                        }
                    }
                }
                const int khB = khA - 1;
                if (khB >= 0 && khB < 3) {
#pragma unroll
                    for (int o = 0; o < 4; ++o) {
                        const float* w = s_w2 + ((((ocg * 4 + o) * 16 + ic) * 3 + khB) * 5);
#pragma unroll
                        for (int kw = 0; kw < 5; ++kw) {
                            const float wv = w[kw];
#pragma unroll
                            for (int j = 0; j < 4; ++j)
                                accB[o][j] = fmaf(wv, in[j + kw], accB[o][j]);
                        }
                    }
                }
            }
        }
#pragma unroll
        for (int o = 0; o < 4; ++o) {
            const int oc = ocg * 4 + o;
            const float bv = s_b2[oc];
#pragma unroll
            for (int p = 0; p < 2; ++p) {
                float m = fmaxf(fmaxf(accA[o][2 * p], accA[o][2 * p + 1]),
                                fmaxf(accB[o][2 * p], accB[o][2 * p + 1]));
                float v = m + bv;
                v = (v >= 0.0f) ? v : 0.01f * v;
                float tv = tanhf(v);
                const int f = oc * 256 + ph * 128 + (pwg * 2 + p);
                out[FLAT_OFF + (size_t)b * 8192 + f] = tv;
                ro0 = fmaf(tv, Wout[2 * f], ro0);
                ro1 = fmaf(tv, Wout[2 * f + 1], ro1);
            }
        }
    }

#pragma unroll
    for (int off = 16; off > 0; off >>= 1) {
        ro0 += __shfl_down_sync(0xffffffffu, ro0, off);
        ro1 += __shfl_down_sync(0xffffffffu, ro1, off);
    }
    const int warp = tid >> 5, lane = tid & 31;
    if (lane == 0) { s_red[warp] = ro0; s_red[8 + warp] = ro1; }
    __syncthreads();
    if (tid == 0) {
        float a = 0.0f, c = 0.0f;
#pragma unroll
        for (int i = 0; i < 8; ++i) { a += s_red[i]; c += s_red[8 + i]; }
        out[OUT2_OFF + (size_t)b * 2 + 0] = a + bout[0];
        out[OUT2_OFF + (size_t)b * 2 + 1] = c + bout[1];
    }
}

// ---------------------------------------------------------------------------
extern "C" void kernel_launch(void* const* d_in, const int* in_sizes, int n_in,
                              void* d_out, int out_size)
{
    const float* r_att   = (const float*)d_in[0];
    const float* p_att   = (const float*)d_in[1];
    const float* r_fun   = (const float*)d_in[2];
    const float* p_fun   = (const float*)d_in[3];
    const int*   idx     = (const int*)  d_in[4];
    const float* W_att1  = (const float*)d_in[5];
    const float* b_att1  = (const float*)d_in[6];
    const float* W_att2  = (const float*)d_in[7];
    const float* b_att2  = (const float*)d_in[8];
    const float* W_fun1  = (const float*)d_in[9];
    const float* b_fun1  = (const float*)d_in[10];
    const float* W_fun2  = (const float*)d_in[11];
    const float* b_fun2  = (const float*)d_in[12];
    const float* conv1_w = (const float*)d_in[13];
    const float* conv1_b = (const float*)d_in[14];
    const float* conv2_w = (const float*)d_in[15];
    const float* conv2_b = (const float*)d_in[16];
    const float* W_out   = (const float*)d_in[17];
    const float* b_out   = (const float*)d_in[18];
    float* out = (float*)d_out;

    float *pAa, *pAf, *pHa, *pHf;
    cudaGetSymbolAddress((void**)&pAa, gAatt);
    cudaGetSymbolAddress((void**)&pAf, gAfun);
    cudaGetSymbolAddress((void**)&pHa, gHa);
    cudaGetSymbolAddress((void**)&pHf, gHf);

    const size_t conv_smem = SMTOT * sizeof(float);
    cudaFuncSetAttribute(conv_head_k, cudaFuncAttributeMaxDynamicSharedMemorySize,
                         (int)conv_smem);

    // 0,1: concat+pad copies (separate buffers -> no false deps)
    convA_f32<<<dim3((KP_FUN + 255) / 256, M_TOT), 256>>>(r_fun, p_fun, N_R, FUN_IN, KP_FUN, pAf);
    convA_f32<<<dim3((KP_ATT + 255) / 256, M_TOT), 256>>>(r_att, p_att, N_R, SIZE_R, KP_ATT, pAa);

    // 2: att layer1  gelu(A @ W_att1 + b) -> gHa
    sgemm_k<128, 8, 0><<<dim3(ATT_H / 128, (M_TOT + 127) / 128), 256>>>(
        pAa, KP_ATT, M_TOT, KP_ATT, SIZE_R, W_att1, ATT_H, b_att1,
        nullptr, pHa, ATT_H, 0);

    // 3: fun layer1  gelu(A @ W_fun1 + b) -> gHf   (big one; ncu target slot)
    sgemm_k<128, 8, 0><<<dim3(FUN_H / 128, (M_TOT + 127) / 128), 256>>>(
        pAf, KP_FUN, M_TOT, KP_FUN, FUN_IN, W_fun1, FUN_H, b_fun1,
        nullptr, pHf, FUN_H, 0);

    // 4: att layer2  sigmoid(gHa @ W_att2 + b) -> d_out cols [0,256)
    sgemm_k<64, 4, 1><<<dim3(256 / 64, (M_TOT + 127) / 128), 256>>>(
        pHa, ATT_H, M_TOT, ATT_H, ATT_H, W_att2, 256, b_att2,
        out, nullptr, 0, 0);

    // 5: fun layer2  sigmoid(gHf @ W_fun2 + b) -> d_out cols [256,512)
    sgemm_k<64, 4, 1><<<dim3(256 / 64, (M_TOT + 127) / 128), 256>>>(
        pHf, FUN_H, M_TOT, FUN_H, FUN_H, W_fun2, 256, b_fun2,
        out, nullptr, 0, 256);

    // 6: CNN head
    conv_head_k<<<BATCH, 256, conv_smem>>>(
        conv1_w, conv1_b, conv2_w, conv2_b, idx, W_out, b_out, out);

    (void)in_sizes; (void)n_in; (void)out_size;
}

// round 10
// speedup vs baseline: 1.5875x; 1.5875x over previous
#include <cuda_runtime.h>
#include <cstdint>

// ---------------------------------------------------------------------------
// Problem constants
// ---------------------------------------------------------------------------
#define N_R       2000
#define N_P       1512
#define M_TOT     3512
#define SIZE_R    3000
#define FUN_IN    5603
#define ATT_H     2048
#define FUN_H     4096
#define DFEAT     512
#define BATCH     8192
#define KP_ATT    3008          // SIZE_R padded to 16
#define KP_FUN    5616          // FUN_IN padded to 16

#define EP_OFF    (N_R * DFEAT)
#define OUT2_OFF  (EP_OFF + N_P * DFEAT)
#define FLAT_OFF  (OUT2_OFF + BATCH * 2)

// ---------------------------------------------------------------------------
// packed f32x2 helpers (FFMA2 — sm_100-family base ISA, ptxas-encodable)
// ---------------------------------------------------------------------------
typedef unsigned long long ull;
#define PACKF2(d, lo, hi) asm("mov.b64 %0, {%1, %2};" : "=l"(d) : "f"(lo), "f"(hi))
#define FMAF2(acc, a, b)  asm("fma.rn.f32x2 %0, %1, %2, %0;" : "+l"(acc) : "l"(a), "l"(b))
#define UNPKF2(lo, hi, v) asm("mov.b64 {%0, %1}, %2;" : "=f"(lo), "=f"(hi) : "l"(v))

// ---------------------------------------------------------------------------
// fp32 scratch
// ---------------------------------------------------------------------------
__device__ __align__(256) float gAatt[(size_t)M_TOT * KP_ATT];
__device__ __align__(256) float gAfun[(size_t)M_TOT * KP_FUN];
__device__ __align__(256) float gHa[(size_t)M_TOT * ATT_H];
__device__ __align__(256) float gHf[(size_t)M_TOT * FUN_H];

// ---------------------------------------------------------------------------
// concat + pad copy
// ---------------------------------------------------------------------------
__global__ void convA_f32(const float* __restrict__ A0, const float* __restrict__ A1,
                          int split, int K, int Kpad, float* __restrict__ dst)
{
    const int k = blockIdx.x * 256 + threadIdx.x;
    const int m = blockIdx.y;
    if (k >= Kpad) return;
    float x = 0.0f;
    if (k < K)
        x = (m < split) ? A0[(size_t)m * K + k] : A1[(size_t)(m - split) * K + k];
    dst[(size_t)m * Kpad + k] = x;
}

// ---------------------------------------------------------------------------
// FFMA2 SGEMM: C(M,N) = act( A(M,lda) @ W(K,N) + bias )   (exact fp32)
//   BM=128, BK=16, 256 threads, per-thread TM=8 x TN (8 or 4), f32x2 inner.
// EPI 0: gelu  -> H[gm*ldh + gn]
// EPI 1: sigmoid -> scatter to d_out e_r/e_p at column colOff+gn
// ---------------------------------------------------------------------------
template <int BN, int TN, int EPI>
__global__ __launch_bounds__(256, 2)
void sgemm_k(const float* __restrict__ A, int lda, int M, int Kpad, int Kreal,
             const float* __restrict__ W, int N,
             const float* __restrict__ bias,
             float* __restrict__ outp, float* __restrict__ H, int ldh, int colOff)
{
    constexpr int BM = 128, BK = 16, TM = 8;
    constexpr int ASTR = BM + 4;
    constexpr int NF = BN / 64;             // B float4s per thread (2 or 1)
    constexpr int TP = TN / 2;              // acc pairs per row
    static_assert((BM / TM) * (BN / TN) == 256, "256 threads");

    __shared__ float As[2][BK * ASTR];
    __shared__ float Bs[2][BK * BN];

    const int tid = threadIdx.x;
    const int tx  = tid & 15;
    const int ty  = tid >> 4;
    const int bm0 = blockIdx.y * BM;
    const int bn0 = blockIdx.x * BN;

    const int arow = tid >> 1;
    const int ak   = (tid & 1) * 8;
    int gmA = bm0 + arow; if (gmA >= M) gmA = M - 1;   // clamp; results discarded
    const float* Aptr = A + (size_t)gmA * lda + ak;

    const int bkr = tid >> 4;
    const int bnf = tid & 15;

    float4 ra0, ra1, rb[NF];

    ull acc2[TM][TP];
#pragma unroll
    for (int i = 0; i < TM; ++i)
#pragma unroll
        for (int j = 0; j < TP; ++j) acc2[i][j] = 0ULL;   // (0.0f, 0.0f)

    auto ldg = [&](int kt) {
        ra0 = *reinterpret_cast<const float4*>(Aptr + kt);
        ra1 = *reinterpret_cast<const float4*>(Aptr + kt + 4);
        const int gk = kt + bkr;
        if (gk < Kreal) {
            const float* Wr = W + (size_t)gk * N + bn0;
#pragma unroll
            for (int f = 0; f < NF; ++f)
                rb[f] = *reinterpret_cast<const float4*>(Wr + (bnf + f * 16) * 4);
        } else {
#pragma unroll
            for (int f = 0; f < NF; ++f) rb[f] = make_float4(0.f, 0.f, 0.f, 0.f);
        }
    };
    auto sts = [&](int b) {
        float av[8] = {ra0.x, ra0.y, ra0.z, ra0.w, ra1.x, ra1.y, ra1.z, ra1.w};
#pragma unroll
        for (int i = 0; i < 8; ++i)
            As[b][(ak + i) * ASTR + arow] = av[i];
#pragma unroll
        for (int f = 0; f < NF; ++f)
            *reinterpret_cast<float4*>(&Bs[b][bkr * BN + (bnf + f * 16) * 4]) = rb[f];
    };

    const int nc = Kpad / BK;
    ldg(0);
    sts(0);
    __syncthreads();

    for (int c = 0; c < nc; ++c) {
        if (c + 1 < nc) ldg((c + 1) * BK);
        const int cur = c & 1;
#pragma unroll
        for (int k = 0; k < BK; ++k) {
            float a[TM];
            ull  b2[TP];
            *reinterpret_cast<float4*>(&a[0]) =
                *reinterpret_cast<const float4*>(&As[cur][k * ASTR + ty * 4]);
            *reinterpret_cast<float4*>(&a[4]) =
                *reinterpret_cast<const float4*>(&As[cur][k * ASTR + ty * 4 + 64]);
            {
                ulonglong2 q0 = *reinterpret_cast<const ulonglong2*>(
                    &Bs[cur][k * BN + tx * 4]);
                b2[0] = q0.x; b2[1] = q0.y;
                if constexpr (TN == 8) {
                    ulonglong2 q1 = *reinterpret_cast<const ulonglong2*>(
                        &Bs[cur][k * BN + tx * 4 + 64]);
                    b2[2] = q1.x; b2[3] = q1.y;
                }
            }
#pragma unroll
            for (int i = 0; i < TM; ++i) {
                ull a2; PACKF2(a2, a[i], a[i]);
#pragma unroll
                for (int j = 0; j < TP; ++j)
                    FMAF2(acc2[i][j], a2, b2[j]);
            }
        }
        if (c + 1 < nc) sts((c + 1) & 1);
        __syncthreads();
    }

    // ---- epilogue ----
#pragma unroll
    for (int i = 0; i < TM; ++i) {
        const int gm = bm0 + ty * 4 + (i & 3) + (i >> 2) * 64;
        if (gm >= M) continue;
#pragma unroll
        for (int j = 0; j < TP; ++j) {
            const int gn = bn0 + tx * 4 + (j & 1) * 2 + (j >> 1) * 64;
            float c0, c1;
            UNPKF2(c0, c1, acc2[i][j]);
            const float v0 = c0 + __ldg(bias + gn);
            const float v1 = c1 + __ldg(bias + gn + 1);
            if constexpr (EPI == 0) {
                H[(size_t)gm * ldh + gn]     =
                    0.5f * v0 * (1.0f + erff(v0 * 0.70710678118654752f));
                H[(size_t)gm * ldh + gn + 1] =
                    0.5f * v1 * (1.0f + erff(v1 * 0.70710678118654752f));
            } else {
                float* dst = (gm < N_R)
                                 ? (outp + (size_t)gm * DFEAT + colOff + gn)
                                 : (outp + EP_OFF + (size_t)(gm - N_R) * DFEAT + colOff + gn);
                dst[0] = 1.0f / (1.0f + expf(-v0));
                dst[1] = 1.0f / (1.0f + expf(-v1));
            }
        }
    }
}

// ---------------------------------------------------------------------------
// CNN head — conv2 inner loop converted to f32x2 (pairs over adjacent ow)
// ---------------------------------------------------------------------------
#define SMX    0
#define SMW1   (SMX  + 2 * 516)
#define SMB1   (SMW1 + 240)
#define SMB2   (SMB1 + 16)
#define SMW2   (SMB2 + 32)
#define SMP1   (SMW2 + 7680)
#define SMRED  (SMP1 + 16 * 2 * 260)
#define SMTOT  (SMRED + 16)

__global__ __launch_bounds__(256)
void conv_head_k(const float* __restrict__ w1, const float* __restrict__ b1,
                 const float* __restrict__ w2, const float* __restrict__ b2,
                 const int* __restrict__ idx,
                 const float* __restrict__ Wout, const float* __restrict__ bout,
                 float* __restrict__ out)
{
    extern __shared__ float smf[];
    float* s_x  = smf + SMX;
    float* s_w1 = smf + SMW1;
    float* s_b1 = smf + SMB1;
    float* s_b2 = smf + SMB2;
    float* s_w2 = smf + SMW2;
    float* s_p1 = smf + SMP1;
    float* s_red = smf + SMRED;

    const int tid = threadIdx.x;
    const int b   = blockIdx.x;

    for (int i = tid; i < 2 * 516; i += 256) s_x[i] = 0.0f;
    for (int i = tid; i < 16 * 2 * 260; i += 256) s_p1[i] = 0.0f;
    for (int i = tid; i < 240; i += 256) s_w1[i] = w1[i];
    for (int i = tid; i < 7680; i += 256) s_w2[i] = w2[i];
    if (tid < 16) s_b1[tid] = b1[tid];
    if (tid >= 32 && tid < 64) s_b2[tid - 32] = b2[tid - 32];

    const int id   = idx[b];
    const int r_no = id / 1512;
    const int p_no = id - r_no * 1512;
    __syncthreads();

    for (int c = tid; c < DFEAT; c += 256) {
        s_x[2 + c]        = out[(size_t)r_no * DFEAT + c];
        s_x[516 + 2 + c]  = out[EP_OFF + (size_t)p_no * DFEAT + c];
    }
    __syncthreads();

    // ---- conv1 + leaky + avgpool -> s_p1 (16,2,256) ----
    for (int j = tid; j < 16 * 2 * 256; j += 256) {
        const int oc = j >> 9;
        const int ph = (j >> 8) & 1;
        const int pw = j & 255;
        const float* w = s_w1 + oc * 15;
        const float bv = s_b1[oc];
        float sum = 0.0f;
#pragma unroll
        for (int dh = 0; dh < 2; ++dh) {
            const int oh = 2 * ph + dh;
#pragma unroll
            for (int dw = 0; dw < 2; ++dw) {
                const int ow = 2 * pw + dw;
                float c = 0.0f;
#pragma unroll
                for (int kh = 0; kh < 3; ++kh) {
                    const int ih = oh + kh - 2;
                    if (ih >= 0 && ih < 2) {
#pragma unroll
                        for (int kw = 0; kw < 5; ++kw)
                            c = fmaf(w[kh * 5 + kw], s_x[ih * 516 + ow + kw], c);
                    }
                }
                c += bv;
                sum += (c >= 0.0f) ? c : 0.01f * c;
            }
        }
        s_p1[(oc * 2 + ph) * 260 + 2 + pw] = 0.25f * sum;
    }
    __syncthreads();

    // ---- conv2 (f32x2) + leaky + maxpool + tanh + flat + out-GEMM ----
    float ro0 = 0.0f, ro1 = 0.0f;
#pragma unroll
    for (int pass = 0; pass < 4; ++pass) {
        const int t   = tid + pass * 256;
        const int ocg = t >> 7;
        const int ph  = (t >> 6) & 1;
        const int pwg = t & 63;
        const int ow0 = pwg * 4;

        ull accA2[4][2], accB2[4][2];
#pragma unroll
        for (int o = 0; o < 4; ++o) {
            accA2[o][0] = 0ULL; accA2[o][1] = 0ULL;
            accB2[o][0] = 0ULL; accB2[o][1] = 0ULL;
        }

        const int khA0 = 2 - 2 * ph;
#pragma unroll
        for (int ic = 0; ic < 16; ++ic) {
#pragma unroll
            for (int ih = 0; ih < 2; ++ih) {
                const float* rowp = s_p1 + (ic * 2 + ih) * 260;
                float4 u0 = *reinterpret_cast<const float4*>(rowp + ow0);
                float4 u1 = *reinterpret_cast<const float4*>(rowp + ow0 + 4);
                float in[8] = {u0.x, u0.y, u0.z, u0.w, u1.x, u1.y, u1.z, u1.w};
                ull p2[7];
#pragma unroll
                for (int s = 0; s < 7; ++s) PACKF2(p2[s], in[s], in[s + 1]);

                const int khA = ih + khA0;
                if (khA >= 0 && khA < 3) {
#pragma unroll
                    for (int o = 0; o < 4; ++o) {
                        const float* w = s_w2 + ((((ocg * 4 + o) * 16 + ic) * 3 + khA) * 5);
#pragma unroll
                        for (int kw = 0; kw < 5; ++kw) {
                            ull w2p; PACKF2(w2p, w[kw], w[kw]);
                            FMAF2(accA2[o][0], w2p, p2[kw]);
                            FMAF2(accA2[o][1], w2p, p2[kw + 2]);
                        }
                    }
                }
                const int khB = khA - 1;
                if (khB >= 0 && khB < 3) {
#pragma unroll
                    for (int o = 0; o < 4; ++o) {
                        const float* w = s_w2 + ((((ocg * 4 + o) * 16 + ic) * 3 + khB) * 5);
#pragma unroll
                        for (int kw = 0; kw < 5; ++kw) {
                            ull w2p; PACKF2(w2p, w[kw], w[kw]);
                            FMAF2(accB2[o][0], w2p, p2[kw]);
                            FMAF2(accB2[o][1], w2p, p2[kw + 2]);
                        }
                    }
                }
            }
        }
#pragma unroll
        for (int o = 0; o < 4; ++o) {
            const int oc = ocg * 4 + o;
            const float bv = s_b2[oc];
#pragma unroll
            for (int p = 0; p < 2; ++p) {
                float a0, a1, b0, b1;
                UNPKF2(a0, a1, accA2[o][p]);
                UNPKF2(b0, b1, accB2[o][p]);
                float m = fmaxf(fmaxf(a0, a1), fmaxf(b0, b1));
                float v = m + bv;
                v = (v >= 0.0f) ? v : 0.01f * v;
                float tv = tanhf(v);
                const int f = oc * 256 + ph * 128 + (pwg * 2 + p);
                out[FLAT_OFF + (size_t)b * 8192 + f] = tv;
                ro0 = fmaf(tv, Wout[2 * f], ro0);
                ro1 = fmaf(tv, Wout[2 * f + 1], ro1);
            }
        }
    }

#pragma unroll
    for (int off = 16; off > 0; off >>= 1) {
        ro0 += __shfl_down_sync(0xffffffffu, ro0, off);
        ro1 += __shfl_down_sync(0xffffffffu, ro1, off);
    }
    const int warp = tid >> 5, lane = tid & 31;
    if (lane == 0) { s_red[warp] = ro0; s_red[8 + warp] = ro1; }
    __syncthreads();
    if (tid == 0) {
        float a = 0.0f, c = 0.0f;
#pragma unroll
        for (int i = 0; i < 8; ++i) { a += s_red[i]; c += s_red[8 + i]; }
        out[OUT2_OFF + (size_t)b * 2 + 0] = a + bout[0];
        out[OUT2_OFF + (size_t)b * 2 + 1] = c + bout[1];
    }
}

// ---------------------------------------------------------------------------
extern "C" void kernel_launch(void* const* d_in, const int* in_sizes, int n_in,
                              void* d_out, int out_size)
{
    const float* r_att   = (const float*)d_in[0];
    const float* p_att   = (const float*)d_in[1];
    const float* r_fun   = (const float*)d_in[2];
    const float* p_fun   = (const float*)d_in[3];
    const int*   idx     = (const int*)  d_in[4];
    const float* W_att1  = (const float*)d_in[5];
    const float* b_att1  = (const float*)d_in[6];
    const float* W_att2  = (const float*)d_in[7];
    const float* b_att2  = (const float*)d_in[8];
    const float* W_fun1  = (const float*)d_in[9];
    const float* b_fun1  = (const float*)d_in[10];
    const float* W_fun2  = (const float*)d_in[11];
    const float* b_fun2  = (const float*)d_in[12];
    const float* conv1_w = (const float*)d_in[13];
    const float* conv1_b = (const float*)d_in[14];
    const float* conv2_w = (const float*)d_in[15];
    const float* conv2_b = (const float*)d_in[16];
    const float* W_out   = (const float*)d_in[17];
    const float* b_out   = (const float*)d_in[18];
    float* out = (float*)d_out;

    float *pAa, *pAf, *pHa, *pHf;
    cudaGetSymbolAddress((void**)&pAa, gAatt);
    cudaGetSymbolAddress((void**)&pAf, gAfun);
    cudaGetSymbolAddress((void**)&pHa, gHa);
    cudaGetSymbolAddress((void**)&pHf, gHf);

    const size_t conv_smem = SMTOT * sizeof(float);
    cudaFuncSetAttribute(conv_head_k, cudaFuncAttributeMaxDynamicSharedMemorySize,
                         (int)conv_smem);

    convA_f32<<<dim3((KP_FUN + 255) / 256, M_TOT), 256>>>(r_fun, p_fun, N_R, FUN_IN, KP_FUN, pAf);
    convA_f32<<<dim3((KP_ATT + 255) / 256, M_TOT), 256>>>(r_att, p_att, N_R, SIZE_R, KP_ATT, pAa);

    sgemm_k<128, 8, 0><<<dim3(ATT_H / 128, (M_TOT + 127) / 128), 256>>>(
        pAa, KP_ATT, M_TOT, KP_ATT, SIZE_R, W_att1, ATT_H, b_att1,
        nullptr, pHa, ATT_H, 0);

    sgemm_k<128, 8, 0><<<dim3(FUN_H / 128, (M_TOT + 127) / 128), 256>>>(
        pAf, KP_FUN, M_TOT, KP_FUN, FUN_IN, W_fun1, FUN_H, b_fun1,
        nullptr, pHf, FUN_H, 0);

    sgemm_k<64, 4, 1><<<dim3(256 / 64, (M_TOT + 127) / 128), 256>>>(
        pHa, ATT_H, M_TOT, ATT_H, ATT_H, W_att2, 256, b_att2,
        out, nullptr, 0, 0);

    sgemm_k<64, 4, 1><<<dim3(256 / 64, (M_TOT + 127) / 128), 256>>>(
        pHf, FUN_H, M_TOT, FUN_H, FUN_H, W_fun2, 256, b_fun2,
        out, nullptr, 0, 256);

    conv_head_k<<<BATCH, 256, conv_smem>>>(
        conv1_w, conv1_b, conv2_w, conv2_b, idx, W_out, b_out, out);

    (void)in_sizes; (void)n_in; (void)out_size;
}